// round 4
// baseline (speedup 1.0000x reference)
#include <cuda_runtime.h>
#include <cstdint>

// out[i, :] = weight[b[i], :], out[0, :] = 0.   N=1e6 cells, 32 f32 each.
//
// R3: kernel was LSU-issue-bound (STG.128 = 12 cyc/warp vs STS.128 = 4).
// Stage output tiles in smem (STS.128) and drain with 1D cp.async.bulk
// (TMA store, no per-element LSU cost). Double-buffered 16KB tiles.
// Weight (8KB) read via __ldg -> L1-resident after first wave.

constexpr int BLOCK = 256;
constexpr int TILE_CHUNKS = 1024;                       // float4 per tile = 16KB
constexpr int CPT = TILE_CHUNKS / BLOCK;                // 4 chunks/thread

__device__ __forceinline__ uint32_t smem_u32(const void* p) {
    return (uint32_t)__cvta_generic_to_shared(p);
}

__global__ __launch_bounds__(BLOCK)
void batch_effect_kernel(const int* __restrict__ b,
                         const float4* __restrict__ w,
                         float4* __restrict__ out,
                         unsigned int total_chunks,
                         unsigned int n_tiles)
{
    __shared__ alignas(128) float4 buf[2][TILE_CHUNKS]; // 32 KB

    int tid = threadIdx.x;
    int p = 0;
    unsigned int iter = 0;

    for (unsigned int tile = blockIdx.x; tile < n_tiles;
         tile += gridDim.x, iter++, p ^= 1) {

        unsigned int base = tile * TILE_CHUNKS;
        unsigned int nchunk = total_chunks - base;
        if (nchunk > TILE_CHUNKS) nchunk = TILE_CHUNKS;

        // Buffer p's store was committed 2 iterations ago; allow only the
        // most recent group to still be in flight before overwriting it.
        if (iter >= 2) {
            if (tid == 0)
                asm volatile("cp.async.bulk.wait_group.read 1;" ::: "memory");
            __syncthreads();
        }

        #pragma unroll
        for (int u = 0; u < CPT; u++) {
            unsigned int local = u * BLOCK + tid;       // lane-consecutive
            unsigned int t = base + local;              // global chunk id
            if (local < nchunk) {
                int bi = __ldg(&b[t >> 3]);
                float4 v = __ldg(&w[((unsigned)bi << 3) | (t & 7u)]);
                if (t < 8u) v = make_float4(0.f, 0.f, 0.f, 0.f);
                buf[p][local] = v;                      // STS.128, conflict-free
            }
        }
        __syncthreads();

        if (tid == 0) {
            asm volatile("fence.proxy.async.shared::cta;" ::: "memory");
            asm volatile(
                "cp.async.bulk.global.shared::cta.bulk_group [%0], [%1], %2;"
                :: "l"(out + base), "r"(smem_u32(&buf[p][0])), "r"(nchunk * 16u)
                : "memory");
            asm volatile("cp.async.bulk.commit_group;" ::: "memory");
        }
    }

    // smem must stay alive until all bulk stores have read it
    if (tid == 0)
        asm volatile("cp.async.bulk.wait_group.read 0;" ::: "memory");
}

extern "C" void kernel_launch(void* const* d_in, const int* in_sizes, int n_in,
                              void* d_out, int out_size)
{
    const int* b = (const int*)d_in[0];          // [N, 1] int32
    const float4* w = (const float4*)d_in[1];    // [64, 32] f32 = 512 float4
    float4* out = (float4*)d_out;                // [N, 32] f32 = N*8 float4

    unsigned int n_cells = (unsigned int)in_sizes[0];
    unsigned int total_chunks = n_cells * 8u;                    // 8e6
    unsigned int n_tiles = (total_chunks + TILE_CHUNKS - 1) / TILE_CHUNKS;

    unsigned int grid = 148u * 7u;               // 7 CTAs/SM (32KB smem each)
    if (grid > n_tiles) grid = n_tiles;

    batch_effect_kernel<<<grid, BLOCK>>>(b, w, out, total_chunks, n_tiles);
}

// round 5
// speedup vs baseline: 1.1829x; 1.1829x over previous
#include <cuda_runtime.h>
#include <cstdint>

// out[i, :] = weight[b[i], :], out[0, :] = 0.   N=1e6 cells, 32 f32 each.
//
// R5: back to the proven direct-STG structure (R2), doubled ILP:
//  - U=16 block-strided float4 chunks per thread; all 16 index LDGs issued
//    up front (16 outstanding loads per thread)
//  - weight table (8KB) in smem -> dependent gather is LDS (4cyc/warp-512B)
//  - st.global.cs streaming stores (write-once data, evict-first in L2)

constexpr int BLOCK = 256;
constexpr int U = 16;

__device__ __forceinline__ void stg_cs(float4* p, float4 v) {
    asm volatile("st.global.cs.v4.f32 [%0], {%1,%2,%3,%4};"
                 :: "l"(p), "f"(v.x), "f"(v.y), "f"(v.z), "f"(v.w)
                 : "memory");
}

__global__ __launch_bounds__(BLOCK)
void batch_effect_kernel(const int* __restrict__ b,
                         const float4* __restrict__ w,
                         float4* __restrict__ out,
                         unsigned int total_chunks)
{
    __shared__ float4 sw[512];            // 64 rows x 8 float4 = 8 KB
    #pragma unroll
    for (int i = threadIdx.x; i < 512; i += BLOCK)
        sw[i] = w[i];
    __syncthreads();

    unsigned int base = blockIdx.x * (BLOCK * U) + threadIdx.x;

    if (base + (U - 1) * BLOCK < total_chunks) {
        // Full tile: issue all 16 index loads first -> MLP=16 per thread.
        int bi[U];
        #pragma unroll
        for (int u = 0; u < U; u++) {
            unsigned int t = base + u * BLOCK;
            bi[u] = __ldg(&b[t >> 3]);
        }
        #pragma unroll
        for (int u = 0; u < U; u++) {
            unsigned int t = base + u * BLOCK;
            float4 v = sw[((unsigned)bi[u] << 3) | (t & 7u)];
            if (t < 8u) v = make_float4(0.f, 0.f, 0.f, 0.f);
            stg_cs(&out[t], v);
        }
    } else {
        // Tail tile
        #pragma unroll
        for (int u = 0; u < U; u++) {
            unsigned int t = base + u * BLOCK;
            if (t < total_chunks) {
                int bi = __ldg(&b[t >> 3]);
                float4 v = sw[((unsigned)bi << 3) | (t & 7u)];
                if (t < 8u) v = make_float4(0.f, 0.f, 0.f, 0.f);
                stg_cs(&out[t], v);
            }
        }
    }
}

extern "C" void kernel_launch(void* const* d_in, const int* in_sizes, int n_in,
                              void* d_out, int out_size)
{
    const int* b = (const int*)d_in[0];          // [N, 1] int32
    const float4* w = (const float4*)d_in[1];    // [64, 32] f32 = 512 float4
    float4* out = (float4*)d_out;                // [N, 32] f32 = N*8 float4

    unsigned int n_cells = (unsigned int)in_sizes[0];
    unsigned int total_chunks = n_cells * 8u;            // 8e6, fits in u32
    unsigned int per_block = BLOCK * U;                  // 4096 chunks per CTA
    unsigned int grid = (total_chunks + per_block - 1) / per_block;

    batch_effect_kernel<<<grid, BLOCK>>>(b, w, out, total_chunks);
}